// round 6
// baseline (speedup 1.0000x reference)
#include <cuda_runtime.h>
#include <math.h>

#define TT    1024
#define BATCH 1024
#define HDIM  100
#define GDIM  400
#define BPB   8              // batch elems per block
#define NB1   (BATCH / BPB)  // 128 persistent blocks
#define NT1   800            // (gp in 0..1) x (bp in 0..3) x (j0 in 0..99)

typedef unsigned long long u64;

__device__ float g_h1[(size_t)TT * BATCH * HDIM];    // layer-0 hidden states
__device__ float g_pre1[(size_t)TT * BATCH * GDIM];  // layer-1 gate pre-activations

__device__ __forceinline__ float sigmf(float x) { return 1.0f / (1.0f + __expf(-x)); }
__device__ __forceinline__ float tanh_fast(float x) {
    float t = __expf(2.0f * x);
    return 1.0f - __fdividef(2.0f, t + 1.0f);
}

__device__ __forceinline__ u64 ffma2(u64 a, u64 b, u64 c) {
    u64 d;
    asm("fma.rn.f32x2 %0, %1, %2, %3;" : "=l"(d) : "l"(a), "l"(b), "l"(c));
    return d;
}
__device__ __forceinline__ float hsum2(u64 v) {
    float lo, hi;
    asm("mov.b64 {%0, %1}, %2;" : "=f"(lo), "=f"(hi) : "l"(v));
    return lo + hi;
}

// ============================================================================
// Layer-0 recurrence. 800 threads: gp (warp-uniform) picks gate pair
// (gp=0 -> i,g ; gp=1 -> f,o); thread computes those 2 gates for 2 batch
// elems. Gate halves exchanged via smem; cell state in registers.
// ============================================================================
__global__ void __launch_bounds__(NT1, 1) lstm_layer0_kernel(
    const float* __restrict__ x,      // [1024][3][1024]
    const float* __restrict__ Wih,    // [400][3]
    const float* __restrict__ Whh,    // [400][100]
    const float* __restrict__ bih,
    const float* __restrict__ bhh)
{
    extern __shared__ float sm[];
    float* sW    = sm;                   // 400*100
    float* sWin  = sW + GDIM * HDIM;     // 400*4
    float* sBias = sWin + GDIM * 4;      // 400
    float* sH    = sBias + GDIM;         // 800
    float* sP    = sH + BPB * HDIM;      // 800  sig(i)*tanh(g)
    float* sF    = sP + BPB * HDIM;      // 800  sig(f)
    float* sO    = sF + BPB * HDIM;      // 800  sig(o)

    const int tid = threadIdx.x;
    const int gp  = (tid >= 400) ? 1 : 0;
    const int r   = tid - gp * 400;
    const int bp  = r & 3;
    const int j0  = r >> 2;              // 0..99
    const int b0  = 2 * bp, b1 = b0 + 1;
    const int bu  = 2 * bp + gp;         // batch elem this thread updates
    const int gA  = gp;                  // gate row block A: i or f
    const int gB  = gp + 2;              // gate row block B: g or o
    const int bg0 = blockIdx.x * BPB;

    for (int lin = tid; lin < GDIM * HDIM; lin += NT1) sW[lin] = Whh[lin];
    for (int lin = tid; lin < GDIM * 3; lin += NT1)
        sWin[(lin / 3) * 4 + (lin % 3)] = Wih[lin];
    for (int lin = tid; lin < GDIM; lin += NT1) sBias[lin] = bih[lin] + bhh[lin];
    for (int lin = tid; lin < BPB * HDIM; lin += NT1) sH[lin] = 0.0f;
    __syncthreads();

    const float biA = sBias[gA * HDIM + j0];
    const float biB = sBias[gB * HDIM + j0];
    float wiA[3], wiB[3];
    #pragma unroll
    for (int c = 0; c < 3; c++) {
        wiA[c] = sWin[(gA * HDIM + j0) * 4 + c];
        wiB[c] = sWin[(gB * HDIM + j0) * 4 + c];
    }
    const ulonglong2* wpA = (const ulonglong2*)(sW + (gA * HDIM + j0) * HDIM);
    const ulonglong2* wpB = (const ulonglong2*)(sW + (gB * HDIM + j0) * HDIM);
    const float* xa = x + (size_t)(bg0 + b0) * 3072;
    const float* xb = x + (size_t)(bg0 + b1) * 3072;

    float cReg = 0.0f;

    for (int t = 0; t < TT; t++) {
        float xa0 = xa[t], xa1 = xa[1024 + t], xa2 = xa[2048 + t];
        float xb0 = xb[t], xb1 = xb[1024 + t], xb2 = xb[2048 + t];

        u64 aA0 = 0, aA1 = 0, aB0 = 0, aB1 = 0;
        const ulonglong2* hpa = (const ulonglong2*)(sH + b0 * HDIM);
        const ulonglong2* hpb = (const ulonglong2*)(sH + b1 * HDIM);
        #pragma unroll
        for (int k4 = 0; k4 < HDIM / 4; k4++) {
            ulonglong2 ha = hpa[k4];
            ulonglong2 hb = hpb[k4];
            ulonglong2 wA = wpA[k4];
            ulonglong2 wB = wpB[k4];
            aA0 = ffma2(wA.x, ha.x, aA0); aA0 = ffma2(wA.y, ha.y, aA0);
            aA1 = ffma2(wA.x, hb.x, aA1); aA1 = ffma2(wA.y, hb.y, aA1);
            aB0 = ffma2(wB.x, ha.x, aB0); aB0 = ffma2(wB.y, ha.y, aB0);
            aB1 = ffma2(wB.x, hb.x, aB1); aB1 = ffma2(wB.y, hb.y, aB1);
        }

        float gA0 = hsum2(aA0) + biA + wiA[0]*xa0 + wiA[1]*xa1 + wiA[2]*xa2;
        float gA1 = hsum2(aA1) + biA + wiA[0]*xb0 + wiA[1]*xb1 + wiA[2]*xb2;
        float gB0 = hsum2(aB0) + biB + wiB[0]*xa0 + wiB[1]*xa1 + wiB[2]*xa2;
        float gB1 = hsum2(aB1) + biB + wiB[0]*xb0 + wiB[1]*xb1 + wiB[2]*xb2;

        if (gp == 0) {   // warp-uniform branch
            sP[b0 * HDIM + j0] = sigmf(gA0) * tanh_fast(gB0);
            sP[b1 * HDIM + j0] = sigmf(gA1) * tanh_fast(gB1);
        } else {
            sF[b0 * HDIM + j0] = sigmf(gA0);
            sF[b1 * HDIM + j0] = sigmf(gA1);
            sO[b0 * HDIM + j0] = sigmf(gB0);
            sO[b1 * HDIM + j0] = sigmf(gB1);
        }
        __syncthreads();

        // update own batch elem
        cReg = sF[bu * HDIM + j0] * cReg + sP[bu * HDIM + j0];
        float hv = sO[bu * HDIM + j0] * tanh_fast(cReg);
        sH[bu * HDIM + j0] = hv;
        g_h1[((size_t)t * BATCH + bg0 + bu) * HDIM + j0] = hv;
        __syncthreads();
    }
}

// ============================================================================
// Layer-1 input GEMM: pre1[r][j] = bias[j] + sum_k h1[r][k]*W_ih1[j][k]
// ============================================================================
#define GA_MT 128
#define GA_NT 80
__global__ void __launch_bounds__(256, 2) gemm_ih1_kernel(
    const float* __restrict__ W,      // [400][100]
    const float* __restrict__ bih,
    const float* __restrict__ bhh)
{
    extern __shared__ float sm[];
    float* sA = sm;                   // 128*100
    float* sB = sA + GA_MT * HDIM;    // 80*102

    const int tid = threadIdx.x;
    const size_t rbase = (size_t)blockIdx.y * GA_MT;
    const int cbase = blockIdx.x * GA_NT;

    for (int lin = tid; lin < GA_MT * HDIM; lin += 256)
        sA[lin] = g_h1[rbase * HDIM + lin];
    for (int lin = tid; lin < GA_NT * HDIM; lin += 256)
        sB[(lin / HDIM) * 102 + (lin % HDIM)] = W[(size_t)cbase * HDIM + lin];
    __syncthreads();

    const int tx = tid & 15;
    const int ty = tid >> 4;

    u64 acc[8][5];
    #pragma unroll
    for (int i = 0; i < 8; i++)
        #pragma unroll
        for (int u = 0; u < 5; u++) acc[i][u] = 0ULL;

    #pragma unroll 5
    for (int kp = 0; kp < HDIM / 2; kp++) {
        u64 b2[5];
        #pragma unroll
        for (int u = 0; u < 5; u++)
            b2[u] = *(const u64*)(sB + (tx * 5 + u) * 102 + 2 * kp);
        #pragma unroll
        for (int i = 0; i < 8; i++) {
            u64 a2 = *(const u64*)(sA + (ty * 8 + i) * HDIM + 2 * kp);
            #pragma unroll
            for (int u = 0; u < 5; u++)
                acc[i][u] = ffma2(a2, b2[u], acc[i][u]);
        }
    }

    float bias[5];
    #pragma unroll
    for (int u = 0; u < 5; u++) {
        int col = cbase + tx * 5 + u;
        bias[u] = bih[col] + bhh[col];
    }
    #pragma unroll
    for (int i = 0; i < 8; i++) {
        size_t row = rbase + ty * 8 + i;
        #pragma unroll
        for (int u = 0; u < 5; u++)
            g_pre1[row * GDIM + cbase + tx * 5 + u] = hsum2(acc[i][u]) + bias[u];
    }
}

// ============================================================================
// Layer-1 recurrence (pre1 precomputed) + fused 10x100 FC.
// ============================================================================
__global__ void __launch_bounds__(NT1, 1) lstm_layer1_kernel(
    const float* __restrict__ Whh,    // [400][100]
    const float* __restrict__ fcw,    // [10][100]
    const float* __restrict__ fcb,    // [10]
    float* __restrict__ out)          // [1024][10]
{
    extern __shared__ float sm[];
    float* sW = sm;                   // 400*100
    float* sH = sW + GDIM * HDIM;     // 800
    float* sP = sH + BPB * HDIM;      // 800
    float* sF = sP + BPB * HDIM;      // 800
    float* sO = sF + BPB * HDIM;      // 800

    const int tid = threadIdx.x;
    const int gp  = (tid >= 400) ? 1 : 0;
    const int r   = tid - gp * 400;
    const int bp  = r & 3;
    const int j0  = r >> 2;
    const int b0  = 2 * bp, b1 = b0 + 1;
    const int bu  = 2 * bp + gp;
    const int gA  = gp;
    const int gB  = gp + 2;
    const int bg0 = blockIdx.x * BPB;

    for (int lin = tid; lin < GDIM * HDIM; lin += NT1) sW[lin] = Whh[lin];
    for (int lin = tid; lin < BPB * HDIM; lin += NT1) sH[lin] = 0.0f;
    __syncthreads();

    const ulonglong2* wpA = (const ulonglong2*)(sW + (gA * HDIM + j0) * HDIM);
    const ulonglong2* wpB = (const ulonglong2*)(sW + (gB * HDIM + j0) * HDIM);

    float cReg = 0.0f;

    for (int t = 0; t < TT; t++) {
        const float* pra = g_pre1 + ((size_t)t * BATCH + bg0 + b0) * GDIM + j0;
        const float* prb = g_pre1 + ((size_t)t * BATCH + bg0 + b1) * GDIM + j0;
        float pA0 = pra[gA * HDIM], pB0 = pra[gB * HDIM];
        float pA1 = prb[gA * HDIM], pB1 = prb[gB * HDIM];

        u64 aA0 = 0, aA1 = 0, aB0 = 0, aB1 = 0;
        const ulonglong2* hpa = (const ulonglong2*)(sH + b0 * HDIM);
        const ulonglong2* hpb = (const ulonglong2*)(sH + b1 * HDIM);
        #pragma unroll
        for (int k4 = 0; k4 < HDIM / 4; k4++) {
            ulonglong2 ha = hpa[k4];
            ulonglong2 hb = hpb[k4];
            ulonglong2 wA = wpA[k4];
            ulonglong2 wB = wpB[k4];
            aA0 = ffma2(wA.x, ha.x, aA0); aA0 = ffma2(wA.y, ha.y, aA0);
            aA1 = ffma2(wA.x, hb.x, aA1); aA1 = ffma2(wA.y, hb.y, aA1);
            aB0 = ffma2(wB.x, ha.x, aB0); aB0 = ffma2(wB.y, ha.y, aB0);
            aB1 = ffma2(wB.x, hb.x, aB1); aB1 = ffma2(wB.y, hb.y, aB1);
        }

        float gA0 = hsum2(aA0) + pA0;
        float gA1 = hsum2(aA1) + pA1;
        float gB0 = hsum2(aB0) + pB0;
        float gB1 = hsum2(aB1) + pB1;

        if (gp == 0) {
            sP[b0 * HDIM + j0] = sigmf(gA0) * tanh_fast(gB0);
            sP[b1 * HDIM + j0] = sigmf(gA1) * tanh_fast(gB1);
        } else {
            sF[b0 * HDIM + j0] = sigmf(gA0);
            sF[b1 * HDIM + j0] = sigmf(gA1);
            sO[b0 * HDIM + j0] = sigmf(gB0);
            sO[b1 * HDIM + j0] = sigmf(gB1);
        }
        __syncthreads();

        cReg = sF[bu * HDIM + j0] * cReg + sP[bu * HDIM + j0];
        sH[bu * HDIM + j0] = sO[bu * HDIM + j0] * tanh_fast(cReg);
        __syncthreads();
    }

    if (tid < BPB * 10) {
        int bb = tid / 10, o = tid % 10;
        float acc = fcb[o];
        const float* wrow = fcw + o * HDIM;
        const float* hrow = sH + bb * HDIM;
        #pragma unroll 4
        for (int k = 0; k < HDIM; k++) acc = fmaf(wrow[k], hrow[k], acc);
        out[(bg0 + bb) * 10 + o] = acc;
    }
}

// ============================================================================
extern "C" void kernel_launch(void* const* d_in, const int* in_sizes, int n_in,
                              void* d_out, int out_size)
{
    (void)in_sizes; (void)n_in; (void)out_size;
    const float* x    = (const float*)d_in[0];
    const float* Wih0 = (const float*)d_in[1];
    const float* Whh0 = (const float*)d_in[2];
    const float* bih0 = (const float*)d_in[3];
    const float* bhh0 = (const float*)d_in[4];
    const float* Wih1 = (const float*)d_in[5];
    const float* Whh1 = (const float*)d_in[6];
    const float* bih1 = (const float*)d_in[7];
    const float* bhh1 = (const float*)d_in[8];
    const float* fcw  = (const float*)d_in[9];
    const float* fcb  = (const float*)d_in[10];
    float* out = (float*)d_out;

    const size_t smem0 = (size_t)(GDIM * HDIM + GDIM * 4 + GDIM + 4 * BPB * HDIM) * 4;
    const size_t smemA = (size_t)(GA_MT * HDIM + GA_NT * 102) * 4;
    const size_t smem1 = (size_t)(GDIM * HDIM + 4 * BPB * HDIM) * 4;

    cudaFuncSetAttribute(lstm_layer0_kernel, cudaFuncAttributeMaxDynamicSharedMemorySize, (int)smem0);
    cudaFuncSetAttribute(gemm_ih1_kernel,    cudaFuncAttributeMaxDynamicSharedMemorySize, (int)smemA);
    cudaFuncSetAttribute(lstm_layer1_kernel, cudaFuncAttributeMaxDynamicSharedMemorySize, (int)smem1);

    lstm_layer0_kernel<<<NB1, NT1, smem0>>>(x, Wih0, Whh0, bih0, bhh0);

    dim3 g2a(GDIM / GA_NT, (TT * BATCH) / GA_MT);  // (5, 8192)
    gemm_ih1_kernel<<<g2a, 256, smemA>>>(Wih1, bih1, bhh1);

    lstm_layer1_kernel<<<NB1, NT1, smem1>>>(Whh1, fcw, fcb, out);
}

// round 7
// speedup vs baseline: 1.9453x; 1.9453x over previous
#include <cuda_runtime.h>
#include <math.h>

#define TT    1024
#define BATCH 1024
#define HDIM  100
#define GDIM  400
#define BPB   8              // batch elems per block
#define NB1   (BATCH / BPB)  // 128 persistent blocks
#define NT1   800            // (j0 0..99) x (bp 0..3) x (kh 0..1)

#define WSTR  104            // W row stride (words): pad k 100..103 = 0
#define KOFF  52             // kh=1 chunk starts at word 52 (k 52..103)
#define HSTR  132            // h row stride (words)
#define HOFF1 68             // h chunk-1 (k>=52) stored at word 68

typedef unsigned long long u64;

__device__ float g_h1[(size_t)TT * BATCH * HDIM];    // layer-0 hidden states
__device__ float g_pre1[(size_t)TT * BATCH * GDIM];  // layer-1 gate pre-activations

__device__ __forceinline__ float sigmf(float x) { return 1.0f / (1.0f + __expf(-x)); }
__device__ __forceinline__ float tanh_fast(float x) {
    float t = __expf(2.0f * x);
    return 1.0f - __fdividef(2.0f, t + 1.0f);
}
__device__ __forceinline__ u64 ffma2(u64 a, u64 b, u64 c) {
    u64 d;
    asm("fma.rn.f32x2 %0, %1, %2, %3;" : "=l"(d) : "l"(a), "l"(b), "l"(c));
    return d;
}
__device__ __forceinline__ float hsum2(u64 v) {
    float lo, hi;
    asm("mov.b64 {%0, %1}, %2;" : "=f"(lo), "=f"(hi) : "l"(v));
    return lo + hi;
}
__device__ __forceinline__ int hmap(int k) { return (k < KOFF) ? k : k + (HOFF1 - KOFF); }

// ============================================================================
// Layer-0 recurrence: split-K lane pairs, shuffle reduction, 1 barrier/step.
// ============================================================================
__global__ void __launch_bounds__(NT1, 1) lstm_layer0_kernel(
    const float* __restrict__ x,      // [1024][3][1024]
    const float* __restrict__ Wih,    // [400][3]
    const float* __restrict__ Whh,    // [400][100]
    const float* __restrict__ bih,
    const float* __restrict__ bhh)
{
    extern __shared__ float sm[];
    float* sW    = sm;                    // 400*104 (cols 100..103 zero)
    float* sWin  = sW + GDIM * WSTR;      // 400*4
    float* sBias = sWin + GDIM * 4;       // 400
    float* sH0   = sBias + GDIM;          // 8*132
    float* sH1   = sH0 + BPB * HSTR;      // 8*132

    const int tid = threadIdx.x;
    const int j0  = tid >> 3;             // 0..99
    const int r   = tid & 7;
    const int bp  = r >> 1;               // 0..3
    const int kh  = r & 1;                // k-half
    const int b0  = 2 * bp, b1 = b0 + 1;
    const int bu  = b0 + kh;              // batch elem this lane finalizes
    const int bg0 = blockIdx.x * BPB;

    for (int lin = tid; lin < GDIM * WSTR; lin += NT1) {
        int row = lin / WSTR, k = lin % WSTR;
        sW[lin] = (k < HDIM) ? Whh[row * HDIM + k] : 0.0f;
    }
    for (int lin = tid; lin < GDIM * 3; lin += NT1)
        sWin[(lin / 3) * 4 + (lin % 3)] = Wih[lin];
    for (int lin = tid; lin < GDIM; lin += NT1) sBias[lin] = bih[lin] + bhh[lin];
    for (int lin = tid; lin < 2 * BPB * HSTR; lin += NT1) sH0[lin] = 0.0f;  // both bufs + pads
    __syncthreads();

    float bi[4], wi[4][3];
    #pragma unroll
    for (int g = 0; g < 4; g++) {
        bi[g] = sBias[g * HDIM + j0];
        wi[g][0] = sWin[(g * HDIM + j0) * 4 + 0];
        wi[g][1] = sWin[(g * HDIM + j0) * 4 + 1];
        wi[g][2] = sWin[(g * HDIM + j0) * 4 + 2];
    }
    const ulonglong2* wp0 = (const ulonglong2*)(sW + (0 * HDIM + j0) * WSTR + kh * KOFF);
    const ulonglong2* wp1 = (const ulonglong2*)(sW + (1 * HDIM + j0) * WSTR + kh * KOFF);
    const ulonglong2* wp2 = (const ulonglong2*)(sW + (2 * HDIM + j0) * WSTR + kh * KOFF);
    const ulonglong2* wp3 = (const ulonglong2*)(sW + (3 * HDIM + j0) * WSTR + kh * KOFF);
    const float* xu = x + (size_t)(bg0 + bu) * 3072;
    const int hwr = bu * HSTR + hmap(j0);   // own h write slot

    float cReg = 0.0f;
    float* sHr = sH0;
    float* sHw = sH1;

    for (int t = 0; t < TT; t++) {
        float x0 = xu[t], x1 = xu[1024 + t], x2 = xu[2048 + t];

        u64 a00 = 0, a01 = 0, a02 = 0, a03 = 0;   // batch b0, gates i f g o
        u64 a10 = 0, a11 = 0, a12 = 0, a13 = 0;   // batch b1
        const ulonglong2* hpa = (const ulonglong2*)(sHr + b0 * HSTR + kh * HOFF1);
        const ulonglong2* hpb = (const ulonglong2*)(sHr + b1 * HSTR + kh * HOFF1);
        #pragma unroll
        for (int i = 0; i < KOFF / 4; i++) {      // 13 iterations
            ulonglong2 ha = hpa[i];
            ulonglong2 hb = hpb[i];
            ulonglong2 w;
            w = wp0[i];
            a00 = ffma2(w.x, ha.x, a00); a00 = ffma2(w.y, ha.y, a00);
            a10 = ffma2(w.x, hb.x, a10); a10 = ffma2(w.y, hb.y, a10);
            w = wp1[i];
            a01 = ffma2(w.x, ha.x, a01); a01 = ffma2(w.y, ha.y, a01);
            a11 = ffma2(w.x, hb.x, a11); a11 = ffma2(w.y, hb.y, a11);
            w = wp2[i];
            a02 = ffma2(w.x, ha.x, a02); a02 = ffma2(w.y, ha.y, a02);
            a12 = ffma2(w.x, hb.x, a12); a12 = ffma2(w.y, hb.y, a12);
            w = wp3[i];
            a03 = ffma2(w.x, ha.x, a03); a03 = ffma2(w.y, ha.y, a03);
            a13 = ffma2(w.x, hb.x, a13); a13 = ffma2(w.y, hb.y, a13);
        }

        // combine k-halves via lane-pair butterfly, then keep own batch's gates
        float s00 = hsum2(a00), s01 = hsum2(a01), s02 = hsum2(a02), s03 = hsum2(a03);
        float s10 = hsum2(a10), s11 = hsum2(a11), s12 = hsum2(a12), s13 = hsum2(a13);
        s00 += __shfl_xor_sync(0xffffffffu, s00, 1);
        s01 += __shfl_xor_sync(0xffffffffu, s01, 1);
        s02 += __shfl_xor_sync(0xffffffffu, s02, 1);
        s03 += __shfl_xor_sync(0xffffffffu, s03, 1);
        s10 += __shfl_xor_sync(0xffffffffu, s10, 1);
        s11 += __shfl_xor_sync(0xffffffffu, s11, 1);
        s12 += __shfl_xor_sync(0xffffffffu, s12, 1);
        s13 += __shfl_xor_sync(0xffffffffu, s13, 1);

        float G0 = kh ? s10 : s00;
        float G1 = kh ? s11 : s01;
        float G2 = kh ? s12 : s02;
        float G3 = kh ? s13 : s03;
        G0 += bi[0] + wi[0][0]*x0 + wi[0][1]*x1 + wi[0][2]*x2;
        G1 += bi[1] + wi[1][0]*x0 + wi[1][1]*x1 + wi[1][2]*x2;
        G2 += bi[2] + wi[2][0]*x0 + wi[2][1]*x1 + wi[2][2]*x2;
        G3 += bi[3] + wi[3][0]*x0 + wi[3][1]*x1 + wi[3][2]*x2;

        cReg = sigmf(G1) * cReg + sigmf(G0) * tanh_fast(G2);
        float hv = sigmf(G3) * tanh_fast(cReg);
        sHw[hwr] = hv;
        g_h1[((size_t)t * BATCH + bg0 + bu) * HDIM + j0] = hv;

        float* tmp = sHr; sHr = sHw; sHw = tmp;
        __syncthreads();
    }
}

// ============================================================================
// Layer-1 input GEMM (unchanged from R5): pre1 = h1 @ W_ih1^T + bias
// ============================================================================
#define GA_MT 128
#define GA_NT 80
__global__ void __launch_bounds__(256, 2) gemm_ih1_kernel(
    const float* __restrict__ W,      // [400][100]
    const float* __restrict__ bih,
    const float* __restrict__ bhh)
{
    extern __shared__ float sm[];
    float* sA = sm;                   // 128*100
    float* sB = sA + GA_MT * HDIM;    // 80*102

    const int tid = threadIdx.x;
    const size_t rbase = (size_t)blockIdx.y * GA_MT;
    const int cbase = blockIdx.x * GA_NT;

    for (int lin = tid; lin < GA_MT * HDIM; lin += 256)
        sA[lin] = g_h1[rbase * HDIM + lin];
    for (int lin = tid; lin < GA_NT * HDIM; lin += 256)
        sB[(lin / HDIM) * 102 + (lin % HDIM)] = W[(size_t)cbase * HDIM + lin];
    __syncthreads();

    const int tx = tid & 15;
    const int ty = tid >> 4;

    u64 acc[8][5];
    #pragma unroll
    for (int i = 0; i < 8; i++)
        #pragma unroll
        for (int u = 0; u < 5; u++) acc[i][u] = 0ULL;

    #pragma unroll 5
    for (int kp = 0; kp < HDIM / 2; kp++) {
        u64 b2[5];
        #pragma unroll
        for (int u = 0; u < 5; u++)
            b2[u] = *(const u64*)(sB + (tx * 5 + u) * 102 + 2 * kp);
        #pragma unroll
        for (int i = 0; i < 8; i++) {
            u64 a2 = *(const u64*)(sA + (ty * 8 + i) * HDIM + 2 * kp);
            #pragma unroll
            for (int u = 0; u < 5; u++)
                acc[i][u] = ffma2(a2, b2[u], acc[i][u]);
        }
    }

    float bias[5];
    #pragma unroll
    for (int u = 0; u < 5; u++) {
        int col = cbase + tx * 5 + u;
        bias[u] = bih[col] + bhh[col];
    }
    #pragma unroll
    for (int i = 0; i < 8; i++) {
        size_t row = rbase + ty * 8 + i;
        #pragma unroll
        for (int u = 0; u < 5; u++)
            g_pre1[row * GDIM + cbase + tx * 5 + u] = hsum2(acc[i][u]) + bias[u];
    }
}

// ============================================================================
// Layer-1 recurrence: same split-K structure, pre1 from gmem, fused FC tail.
// ============================================================================
__global__ void __launch_bounds__(NT1, 1) lstm_layer1_kernel(
    const float* __restrict__ Whh,    // [400][100]
    const float* __restrict__ fcw,    // [10][100]
    const float* __restrict__ fcb,    // [10]
    float* __restrict__ out)          // [1024][10]
{
    extern __shared__ float sm[];
    float* sW  = sm;                  // 400*104
    float* sH0 = sW + GDIM * WSTR;    // 8*132
    float* sH1 = sH0 + BPB * HSTR;    // 8*132

    const int tid = threadIdx.x;
    const int j0  = tid >> 3;
    const int r   = tid & 7;
    const int bp  = r >> 1;
    const int kh  = r & 1;
    const int b0  = 2 * bp, b1 = b0 + 1;
    const int bu  = b0 + kh;
    const int bg0 = blockIdx.x * BPB;

    for (int lin = tid; lin < GDIM * WSTR; lin += NT1) {
        int row = lin / WSTR, k = lin % WSTR;
        sW[lin] = (k < HDIM) ? Whh[row * HDIM + k] : 0.0f;
    }
    for (int lin = tid; lin < 2 * BPB * HSTR; lin += NT1) sH0[lin] = 0.0f;
    __syncthreads();

    const ulonglong2* wp0 = (const ulonglong2*)(sW + (0 * HDIM + j0) * WSTR + kh * KOFF);
    const ulonglong2* wp1 = (const ulonglong2*)(sW + (1 * HDIM + j0) * WSTR + kh * KOFF);
    const ulonglong2* wp2 = (const ulonglong2*)(sW + (2 * HDIM + j0) * WSTR + kh * KOFF);
    const ulonglong2* wp3 = (const ulonglong2*)(sW + (3 * HDIM + j0) * WSTR + kh * KOFF);
    const float* pbase = g_pre1 + (size_t)(bg0 + bu) * GDIM + j0;
    const int hwr = bu * HSTR + hmap(j0);

    float cReg = 0.0f;
    float* sHr = sH0;
    float* sHw = sH1;

    for (int t = 0; t < TT; t++) {
        const float* pr = pbase + (size_t)t * BATCH * GDIM;
        float p0 = pr[0], p1 = pr[HDIM], p2 = pr[2 * HDIM], p3 = pr[3 * HDIM];

        u64 a00 = 0, a01 = 0, a02 = 0, a03 = 0;
        u64 a10 = 0, a11 = 0, a12 = 0, a13 = 0;
        const ulonglong2* hpa = (const ulonglong2*)(sHr + b0 * HSTR + kh * HOFF1);
        const ulonglong2* hpb = (const ulonglong2*)(sHr + b1 * HSTR + kh * HOFF1);
        #pragma unroll
        for (int i = 0; i < KOFF / 4; i++) {
            ulonglong2 ha = hpa[i];
            ulonglong2 hb = hpb[i];
            ulonglong2 w;
            w = wp0[i];
            a00 = ffma2(w.x, ha.x, a00); a00 = ffma2(w.y, ha.y, a00);
            a10 = ffma2(w.x, hb.x, a10); a10 = ffma2(w.y, hb.y, a10);
            w = wp1[i];
            a01 = ffma2(w.x, ha.x, a01); a01 = ffma2(w.y, ha.y, a01);
            a11 = ffma2(w.x, hb.x, a11); a11 = ffma2(w.y, hb.y, a11);
            w = wp2[i];
            a02 = ffma2(w.x, ha.x, a02); a02 = ffma2(w.y, ha.y, a02);
            a12 = ffma2(w.x, hb.x, a12); a12 = ffma2(w.y, hb.y, a12);
            w = wp3[i];
            a03 = ffma2(w.x, ha.x, a03); a03 = ffma2(w.y, ha.y, a03);
            a13 = ffma2(w.x, hb.x, a13); a13 = ffma2(w.y, hb.y, a13);
        }

        float s00 = hsum2(a00), s01 = hsum2(a01), s02 = hsum2(a02), s03 = hsum2(a03);
        float s10 = hsum2(a10), s11 = hsum2(a11), s12 = hsum2(a12), s13 = hsum2(a13);
        s00 += __shfl_xor_sync(0xffffffffu, s00, 1);
        s01 += __shfl_xor_sync(0xffffffffu, s01, 1);
        s02 += __shfl_xor_sync(0xffffffffu, s02, 1);
        s03 += __shfl_xor_sync(0xffffffffu, s03, 1);
        s10 += __shfl_xor_sync(0xffffffffu, s10, 1);
        s11 += __shfl_xor_sync(0xffffffffu, s11, 1);
        s12 += __shfl_xor_sync(0xffffffffu, s12, 1);
        s13 += __shfl_xor_sync(0xffffffffu, s13, 1);

        float G0 = (kh ? s10 : s00) + p0;
        float G1 = (kh ? s11 : s01) + p1;
        float G2 = (kh ? s12 : s02) + p2;
        float G3 = (kh ? s13 : s03) + p3;

        cReg = sigmf(G1) * cReg + sigmf(G0) * tanh_fast(G2);
        sHw[hwr] = sigmf(G3) * tanh_fast(cReg);

        float* tmp = sHr; sHr = sHw; sHw = tmp;
        __syncthreads();
    }

    if (tid < BPB * 10) {
        int bb = tid / 10, o = tid % 10;
        float acc = fcb[o];
        const float* wrow = fcw + o * HDIM;
        const float* hrow = sHr + bb * HSTR;
        #pragma unroll 4
        for (int k = 0; k < HDIM; k++) acc = fmaf(wrow[k], hrow[hmap(k) - 0] * 0.0f + hrow[hmap(k)], acc) - 0.0f * acc;
        out[(bg0 + bb) * 10 + o] = acc;
    }
}

// ============================================================================
extern "C" void kernel_launch(void* const* d_in, const int* in_sizes, int n_in,
                              void* d_out, int out_size)
{
    (void)in_sizes; (void)n_in; (void)out_size;
    const float* x    = (const float*)d_in[0];
    const float* Wih0 = (const float*)d_in[1];
    const float* Whh0 = (const float*)d_in[2];
    const float* bih0 = (const float*)d_in[3];
    const float* bhh0 = (const float*)d_in[4];
    const float* Wih1 = (const float*)d_in[5];
    const float* Whh1 = (const float*)d_in[6];
    const float* bih1 = (const float*)d_in[7];
    const float* bhh1 = (const float*)d_in[8];
    const float* fcw  = (const float*)d_in[9];
    const float* fcb  = (const float*)d_in[10];
    float* out = (float*)d_out;

    const size_t smem0 = (size_t)(GDIM * WSTR + GDIM * 4 + GDIM + 2 * BPB * HSTR) * 4;
    const size_t smemA = (size_t)(GA_MT * HDIM + GA_NT * 102) * 4;
    const size_t smem1 = (size_t)(GDIM * WSTR + 2 * BPB * HSTR) * 4;

    cudaFuncSetAttribute(lstm_layer0_kernel, cudaFuncAttributeMaxDynamicSharedMemorySize, (int)smem0);
    cudaFuncSetAttribute(gemm_ih1_kernel,    cudaFuncAttributeMaxDynamicSharedMemorySize, (int)smemA);
    cudaFuncSetAttribute(lstm_layer1_kernel, cudaFuncAttributeMaxDynamicSharedMemorySize, (int)smem1);

    lstm_layer0_kernel<<<NB1, NT1, smem0>>>(x, Wih0, Whh0, bih0, bhh0);

    dim3 g2a(GDIM / GA_NT, (TT * BATCH) / GA_MT);  // (5, 8192)
    gemm_ih1_kernel<<<g2a, 256, smemA>>>(Wih1, bih1, bhh1);

    lstm_layer1_kernel<<<NB1, NT1, smem1>>>(Whh1, fcw, fcb, out);
}